// round 2
// baseline (speedup 1.0000x reference)
#include <cuda_runtime.h>

#define B_N 2048
#define H_N 4096
#define E_N 8
#define L_N 512

// ---------------- scratch (no allocations allowed) ----------------
__device__ int   g_counts[E_N];
__device__ int   g_rows[E_N][B_N];
__device__ float g_pen[25];   // [0:8)=Q_e, [8:16)=C_e, [16:24)=L1_e, [24]=SS

// ---------------- init ----------------
__global__ void init_kernel() {
    int t = threadIdx.x;
    if (t < E_N) g_counts[t] = 0;
    if (t < 25)  g_pen[t]    = 0.0f;
}

// ---------------- expert selection ----------------
// e_b = argmax_e( envs[idx[b], e] + gumbel[b, e] )   (first max on ties)
// idx may be int32 or int64 on disk; idx = arange(B), so word[1] tells us:
//   int32 layout: words = 0,1,2,3,...   -> word[1]==1 -> stride 1
//   int64 layout: words = 0,0,1,0,2,... -> word[1]==0 -> stride 2
__global__ void select_kernel(const float* __restrict__ envs,
                              const int* __restrict__ idx32,
                              const float* __restrict__ gumbel) {
    int b = blockIdx.x * blockDim.x + threadIdx.x;
    if (b >= B_N) return;
    int stride = (idx32[1] == 0) ? 2 : 1;
    int r = idx32[(size_t)b * stride];
    if (r < 0) r = 0;
    if (r >= B_N) r = B_N - 1;   // safety clamp (idx rows index envs[B,E])
    const float* ev = envs   + (size_t)r * E_N;
    const float* gv = gumbel + (size_t)b * E_N;
    float best = ev[0] + gv[0];
    int be = 0;
#pragma unroll
    for (int e = 1; e < E_N; e++) {
        float v = ev[e] + gv[e];
        if (v > best) { best = v; be = e; }
    }
    int pos = atomicAdd(&g_counts[be], 1);
    g_rows[be][pos] = b;
}

// ---------------- penalty: one pass over W ----------------
// diff_sq[e] = Q_e - (2/E) C_e + SS/E^2 ;  penalty = mean_e diff_sq[e]/L1_e^2
__global__ void penalty_kernel(const float* __restrict__ W) {
    const int LH4 = (L_N * H_N) / 4;  // 524288 float4 per expert
    const float4* Wv = (const float4*)W;

    float q[8], c[8], l1[8], ss = 0.0f;
#pragma unroll
    for (int e = 0; e < 8; e++) { q[e] = 0.f; c[e] = 0.f; l1[e] = 0.f; }

    int stride = gridDim.x * blockDim.x;
    for (int i = blockIdx.x * blockDim.x + threadIdx.x; i < LH4; i += stride) {
        float4 w[8];
#pragma unroll
        for (int e = 0; e < 8; e++) w[e] = Wv[(size_t)e * LH4 + i];
#pragma unroll
        for (int comp = 0; comp < 4; comp++) {
            float we[8];
#pragma unroll
            for (int e = 0; e < 8; e++) {
                float4 t = w[e];
                we[e] = (comp == 0) ? t.x : (comp == 1) ? t.y : (comp == 2) ? t.z : t.w;
            }
            float s = 0.f;
#pragma unroll
            for (int e = 0; e < 8; e++) s += we[e];
            ss = fmaf(s, s, ss);
#pragma unroll
            for (int e = 0; e < 8; e++) {
                q[e]  = fmaf(we[e], we[e], q[e]);
                c[e]  = fmaf(we[e], s,     c[e]);
                l1[e] += fabsf(we[e]);
            }
        }
    }

    // pack 25 partials, warp-reduce, then block-reduce, then global atomics
    float vals[25];
#pragma unroll
    for (int e = 0; e < 8; e++) { vals[e] = q[e]; vals[8 + e] = c[e]; vals[16 + e] = l1[e]; }
    vals[24] = ss;

#pragma unroll
    for (int k = 0; k < 25; k++)
#pragma unroll
        for (int off = 16; off > 0; off >>= 1)
            vals[k] += __shfl_down_sync(0xFFFFFFFFu, vals[k], off);

    __shared__ float sm[8][25];
    int lane = threadIdx.x & 31, warp = threadIdx.x >> 5;
    if (lane == 0) {
#pragma unroll
        for (int k = 0; k < 25; k++) sm[warp][k] = vals[k];
    }
    __syncthreads();
    if (threadIdx.x == 0) {
        int nw = blockDim.x >> 5;
#pragma unroll
        for (int k = 0; k < 25; k++) {
            float acc = 0.f;
            for (int w = 0; w < nw; w++) acc += sm[w][k];
            atomicAdd(&g_pen[k], acc);
        }
    }
}

__global__ void finalize_kernel(float* __restrict__ pen_out) {
    if (threadIdx.x == 0) {
        float acc = 0.f;
        float ss = g_pen[24];
#pragma unroll
        for (int e = 0; e < 8; e++) {
            float diff = g_pen[e] - 0.25f * g_pen[8 + e] + ss * (1.0f / 64.0f);
            float l1 = g_pen[16 + e];
            acc += diff / (l1 * l1);
        }
        pen_out[0] = acc * 0.125f;
    }
}

// ---------------- grouped GEMM: logits[b,:] = hidden[b,:] @ W[e_b]^T ----------------
// Tile: 64 rows x 64 cols, BK=16, 128 threads, 8x4 micro-tile per thread.
#define TM 64
#define TN 64
#define BK 16
#define SPAD 4   // keeps float4 LDS 16B-aligned (stride 68)

__global__ void __launch_bounds__(128, 8)
gemm_kernel(const float* __restrict__ hidden,
            const float* __restrict__ W,
            float* __restrict__ out) {
    __shared__ float As[BK][TM + SPAD];
    __shared__ float Bs[BK][TN + SPAD];
    __shared__ int rowids[TM];

    int e = blockIdx.z;
    int cnt = g_counts[e];
    int m_base = blockIdx.y * TM;
    if (m_base >= cnt) return;
    int l_base = blockIdx.x * TN;
    int tid = threadIdx.x;

    if (tid < TM) {
        int i = m_base + tid;
        rowids[tid] = (i < cnt) ? g_rows[e][i] : -1;
    }
    __syncthreads();

    const float* Wb = W + ((size_t)e * L_N + l_base) * H_N;

    int tm = (tid >> 4) * 8;   // 0..56
    int tn = (tid & 15) * 4;   // 0..60

    float acc[8][4];
#pragma unroll
    for (int i = 0; i < 8; i++)
#pragma unroll
        for (int j = 0; j < 4; j++) acc[i][j] = 0.f;

    // loader mapping: float4 slot f in [0,256): tile-row = f>>2, f4-col = f&3
    int ra0 = tid >> 2,         ca0 = tid & 3;
    int ra1 = (tid + 128) >> 2, ca1 = (tid + 128) & 3;
    int g0 = rowids[ra0];
    int g1 = rowids[ra1];
    const float* ha0 = (g0 >= 0) ? hidden + (size_t)g0 * H_N + ca0 * 4 : nullptr;
    const float* ha1 = (g1 >= 0) ? hidden + (size_t)g1 * H_N + ca1 * 4 : nullptr;
    const float* hb0 = Wb + (size_t)ra0 * H_N + ca0 * 4;
    const float* hb1 = Wb + (size_t)ra1 * H_N + ca1 * 4;

    for (int k0 = 0; k0 < H_N; k0 += BK) {
        float4 va0 = ha0 ? *(const float4*)(ha0 + k0) : make_float4(0.f, 0.f, 0.f, 0.f);
        float4 va1 = ha1 ? *(const float4*)(ha1 + k0) : make_float4(0.f, 0.f, 0.f, 0.f);
        float4 vb0 = *(const float4*)(hb0 + k0);
        float4 vb1 = *(const float4*)(hb1 + k0);

        As[ca0 * 4 + 0][ra0] = va0.x; As[ca0 * 4 + 1][ra0] = va0.y;
        As[ca0 * 4 + 2][ra0] = va0.z; As[ca0 * 4 + 3][ra0] = va0.w;
        As[ca1 * 4 + 0][ra1] = va1.x; As[ca1 * 4 + 1][ra1] = va1.y;
        As[ca1 * 4 + 2][ra1] = va1.z; As[ca1 * 4 + 3][ra1] = va1.w;
        Bs[ca0 * 4 + 0][ra0] = vb0.x; Bs[ca0 * 4 + 1][ra0] = vb0.y;
        Bs[ca0 * 4 + 2][ra0] = vb0.z; Bs[ca0 * 4 + 3][ra0] = vb0.w;
        Bs[ca1 * 4 + 0][ra1] = vb1.x; Bs[ca1 * 4 + 1][ra1] = vb1.y;
        Bs[ca1 * 4 + 2][ra1] = vb1.z; Bs[ca1 * 4 + 3][ra1] = vb1.w;
        __syncthreads();

#pragma unroll
        for (int k = 0; k < BK; k++) {
            float4 a0 = *(const float4*)(&As[k][tm]);
            float4 a1 = *(const float4*)(&As[k][tm + 4]);
            float4 b0 = *(const float4*)(&Bs[k][tn]);
            float a[8] = {a0.x, a0.y, a0.z, a0.w, a1.x, a1.y, a1.z, a1.w};
            float b[4] = {b0.x, b0.y, b0.z, b0.w};
#pragma unroll
            for (int i = 0; i < 8; i++)
#pragma unroll
                for (int j = 0; j < 4; j++)
                    acc[i][j] = fmaf(a[i], b[j], acc[i][j]);
        }
        __syncthreads();
    }

#pragma unroll
    for (int i = 0; i < 8; i++) {
        int grow = rowids[tm + i];
        if (grow >= 0) {
            float4 v = make_float4(acc[i][0], acc[i][1], acc[i][2], acc[i][3]);
            *(float4*)(out + (size_t)grow * L_N + l_base + tn) = v;
        }
    }
}

// ---------------- launch ----------------
extern "C" void kernel_launch(void* const* d_in, const int* in_sizes, int n_in,
                              void* d_out, int out_size) {
    const float* hidden = (const float*)d_in[0];
    const float* envs   = (const float*)d_in[1];
    const int*   idx32  = (const int*)d_in[2];
    const float* gumbel = (const float*)d_in[3];
    const float* W      = (const float*)d_in[4];
    float* out = (float*)d_out;

    init_kernel<<<1, 32>>>();
    select_kernel<<<(B_N + 255) / 256, 256>>>(envs, idx32, gumbel);
    penalty_kernel<<<512, 256>>>(W);

    dim3 ggrid(L_N / TN, B_N / TM, E_N);
    gemm_kernel<<<ggrid, 128>>>(hidden, W, out);

    if (out_size > B_N * L_N)
        finalize_kernel<<<1, 32>>>(out + (size_t)B_N * L_N);
}

// round 3
// speedup vs baseline: 4.1312x; 4.1312x over previous
#include <cuda_runtime.h>
#include <cuda_bf16.h>
#include <cstdint>

#define B_N 2048
#define H_N 4096
#define E_N 8
#define L_N 512

// ---------------- scratch ----------------
__device__ int   g_counts[E_N];
__device__ int   g_rows[E_N][B_N];
__device__ float g_pen[25];   // [0:8)=Q_e, [8:16)=C_e, [16:24)=L1_e, [24]=SS

__global__ void init_kernel() {
    int t = threadIdx.x;
    if (t < E_N) g_counts[t] = 0;
    if (t < 25)  g_pen[t]    = 0.0f;
}

// ---------------- expert selection ----------------
__global__ void select_kernel(const float* __restrict__ envs,
                              const int* __restrict__ idx32,
                              const float* __restrict__ gumbel) {
    int b = blockIdx.x * blockDim.x + threadIdx.x;
    if (b >= B_N) return;
    int stride = (idx32[1] == 0) ? 2 : 1;   // int64-on-disk detection (idx = arange)
    int r = idx32[(size_t)b * stride];
    if (r < 0) r = 0;
    if (r >= B_N) r = B_N - 1;
    const float* ev = envs   + (size_t)r * E_N;
    const float* gv = gumbel + (size_t)b * E_N;
    float best = ev[0] + gv[0];
    int be = 0;
#pragma unroll
    for (int e = 1; e < E_N; e++) {
        float v = ev[e] + gv[e];
        if (v > best) { best = v; be = e; }
    }
    int pos = atomicAdd(&g_counts[be], 1);
    g_rows[be][pos] = b;
}

// ---------------- penalty: one pass over W ----------------
__global__ void __launch_bounds__(256)
penalty_kernel(const float* __restrict__ W) {
    const int LH4 = (L_N * H_N) / 4;
    const float4* Wv = (const float4*)W;

    float q[8], c[8], l1[8], ss = 0.0f;
#pragma unroll
    for (int e = 0; e < 8; e++) { q[e] = 0.f; c[e] = 0.f; l1[e] = 0.f; }

    int stride = gridDim.x * blockDim.x;
    for (int i = blockIdx.x * blockDim.x + threadIdx.x; i < LH4; i += stride) {
        float4 w[8];
#pragma unroll
        for (int e = 0; e < 8; e++) w[e] = Wv[(size_t)e * LH4 + i];
#pragma unroll
        for (int comp = 0; comp < 4; comp++) {
            float we[8];
#pragma unroll
            for (int e = 0; e < 8; e++) {
                float4 t = w[e];
                we[e] = (comp == 0) ? t.x : (comp == 1) ? t.y : (comp == 2) ? t.z : t.w;
            }
            float s = 0.f;
#pragma unroll
            for (int e = 0; e < 8; e++) s += we[e];
            ss = fmaf(s, s, ss);
#pragma unroll
            for (int e = 0; e < 8; e++) {
                q[e]  = fmaf(we[e], we[e], q[e]);
                c[e]  = fmaf(we[e], s,     c[e]);
                l1[e] += fabsf(we[e]);
            }
        }
    }

    // transpose-reduce in smem (replaces 125 serial shuffles/thread)
    __shared__ float red[25][265];   // stride 265: (9k + j) mod 32 conflict-free
    int tid = threadIdx.x;
#pragma unroll
    for (int e = 0; e < 8; e++) {
        red[e][tid]      = q[e];
        red[8 + e][tid]  = c[e];
        red[16 + e][tid] = l1[e];
    }
    red[24][tid] = ss;
    __syncthreads();
    if (tid < 25) {
        float s = 0.f;
#pragma unroll 8
        for (int j = 0; j < 256; j++) s += red[tid][j];
        atomicAdd(&g_pen[tid], s);
    }
}

__global__ void finalize_kernel(float* __restrict__ pen_out) {
    if (threadIdx.x == 0) {
        float acc = 0.f;
        float ss = g_pen[24];
#pragma unroll
        for (int e = 0; e < 8; e++) {
            float diff = g_pen[e] - 0.25f * g_pen[8 + e] + ss * (1.0f / 64.0f);
            float l1 = g_pen[16 + e];
            acc += diff / (l1 * l1);
        }
        pen_out[0] = acc * 0.125f;
    }
}

// ---------------- tensor-core grouped GEMM ----------------
// logits[b,:] = hidden[b,:] @ W[e_b]^T, bf16 split precision (hi+lo), fp32 accum.
// CTA tile 128(M) x 64(N) x 32(K). 256 threads = 8 warps (4 along M x 2 along N),
// warp tile 32x32 -> mma m16n8k16: 2 m-tiles x 4 n-tiles.

#define TM 128
#define TN 64
#define TK 32
#define ASTR 40   // smem row stride in halves (80B): ldmatrix conflict-free

__device__ __forceinline__ uint32_t s2u(const void* p) {
    return (uint32_t)__cvta_generic_to_shared(p);
}

#define LDSM4(r0, r1, r2, r3, a) \
    asm volatile("ldmatrix.sync.aligned.m8n8.x4.shared.b16 {%0,%1,%2,%3}, [%4];" \
                 : "=r"(r0), "=r"(r1), "=r"(r2), "=r"(r3) : "r"(a))

#define MMA16816(d, A, b0, b1) \
    asm volatile("mma.sync.aligned.m16n8k16.row.col.f32.bf16.bf16.f32 " \
                 "{%0,%1,%2,%3}, {%4,%5,%6,%7}, {%8,%9}, {%0,%1,%2,%3};" \
                 : "+f"((d)[0]), "+f"((d)[1]), "+f"((d)[2]), "+f"((d)[3]) \
                 : "r"((A)[0]), "r"((A)[1]), "r"((A)[2]), "r"((A)[3]), \
                   "r"(b0), "r"(b1))

__global__ void __launch_bounds__(256)
gemm_kernel(const float* __restrict__ hidden,
            const float* __restrict__ W,
            float* __restrict__ out) {
    __shared__ __nv_bfloat16 Ah[TM][ASTR];
    __shared__ __nv_bfloat16 Al[TM][ASTR];
    __shared__ __nv_bfloat16 Bh[TN][ASTR];
    __shared__ __nv_bfloat16 Bl[TN][ASTR];
    __shared__ int rowids[TM];

    int e = blockIdx.z;
    int cnt = g_counts[e];
    int m_base = blockIdx.y * TM;
    if (m_base >= cnt) return;
    int l_base = blockIdx.x * TN;
    int tid = threadIdx.x;

    if (tid < TM) {
        int i = m_base + tid;
        rowids[tid] = (i < cnt) ? g_rows[e][i] : -1;
    }
    __syncthreads();

    // ---- loader setup: A = 4 float4 slots/thread, B = 2 slots/thread ----
    const float* aptr[4];
    int arow[4], acol[4];
#pragma unroll
    for (int i = 0; i < 4; i++) {
        int f = tid + i * 256;           // 1024 slots: row = f>>3, col4 = f&7
        arow[i] = f >> 3; acol[i] = (f & 7) * 4;
        int g = rowids[arow[i]];
        aptr[i] = (g >= 0) ? hidden + (size_t)g * H_N + acol[i] : nullptr;
    }
    const float* Wb = W + ((size_t)e * L_N + l_base) * H_N;
    const float* bptr[2];
    int brow[2], bcol[2];
#pragma unroll
    for (int i = 0; i < 2; i++) {
        int f = tid + i * 256;           // 512 slots
        brow[i] = f >> 3; bcol[i] = (f & 7) * 4;
        bptr[i] = Wb + (size_t)brow[i] * H_N + bcol[i];
    }

    int wid = tid >> 5, lane = tid & 31;
    int wm = (wid & 3) * 32;
    int wn = (wid >> 2) * 32;

    float acc[2][4][4];
#pragma unroll
    for (int mt = 0; mt < 2; mt++)
#pragma unroll
        for (int nt = 0; nt < 4; nt++)
#pragma unroll
            for (int j = 0; j < 4; j++) acc[mt][nt][j] = 0.f;

    // ldmatrix addresses (fixed per thread, vary only with ks)
    int a_r = (lane & 15), a_k8 = (lane >> 4) << 3;
    int b_g = lane >> 3, b_sub = b_g >> 1, b_kh = (b_g & 1) << 3, b_r = lane & 7;

    float4 va[4], vb[2];
#pragma unroll
    for (int i = 0; i < 4; i++)
        va[i] = aptr[i] ? *(const float4*)(aptr[i]) : make_float4(0.f, 0.f, 0.f, 0.f);
#pragma unroll
    for (int i = 0; i < 2; i++) vb[i] = *(const float4*)(bptr[i]);

    for (int k0 = 0; k0 < H_N; k0 += TK) {
        __syncthreads();   // previous compute done reading smem
        // convert + store hi/lo
#pragma unroll
        for (int i = 0; i < 4; i++) {
            float4 v = va[i];
            __nv_bfloat162 h01 = __floats2bfloat162_rn(v.x, v.y);
            __nv_bfloat162 h23 = __floats2bfloat162_rn(v.z, v.w);
            __nv_bfloat162 l01 = __floats2bfloat162_rn(v.x - __bfloat162float(h01.x),
                                                       v.y - __bfloat162float(h01.y));
            __nv_bfloat162 l23 = __floats2bfloat162_rn(v.z - __bfloat162float(h23.x),
                                                       v.w - __bfloat162float(h23.y));
            *(__nv_bfloat162*)&Ah[arow[i]][acol[i]]     = h01;
            *(__nv_bfloat162*)&Ah[arow[i]][acol[i] + 2] = h23;
            *(__nv_bfloat162*)&Al[arow[i]][acol[i]]     = l01;
            *(__nv_bfloat162*)&Al[arow[i]][acol[i] + 2] = l23;
        }
#pragma unroll
        for (int i = 0; i < 2; i++) {
            float4 v = vb[i];
            __nv_bfloat162 h01 = __floats2bfloat162_rn(v.x, v.y);
            __nv_bfloat162 h23 = __floats2bfloat162_rn(v.z, v.w);
            __nv_bfloat162 l01 = __floats2bfloat162_rn(v.x - __bfloat162float(h01.x),
                                                       v.y - __bfloat162float(h01.y));
            __nv_bfloat162 l23 = __floats2bfloat162_rn(v.z - __bfloat162float(h23.x),
                                                       v.w - __bfloat162float(h23.y));
            *(__nv_bfloat162*)&Bh[brow[i]][bcol[i]]     = h01;
            *(__nv_bfloat162*)&Bh[brow[i]][bcol[i] + 2] = h23;
            *(__nv_bfloat162*)&Bl[brow[i]][bcol[i]]     = l01;
            *(__nv_bfloat162*)&Bl[brow[i]][bcol[i] + 2] = l23;
        }
        __syncthreads();

        // prefetch next k-tile while tensor cores run
        int kn = k0 + TK;
        if (kn < H_N) {
#pragma unroll
            for (int i = 0; i < 4; i++)
                va[i] = aptr[i] ? *(const float4*)(aptr[i] + kn)
                                : make_float4(0.f, 0.f, 0.f, 0.f);
#pragma unroll
            for (int i = 0; i < 2; i++) vb[i] = *(const float4*)(bptr[i] + kn);
        }

#pragma unroll
        for (int ks = 0; ks < TK; ks += 16) {
            uint32_t ah[2][4], al[2][4], bh[4][2], bl[4][2];
#pragma unroll
            for (int mt = 0; mt < 2; mt++) {
                uint32_t ad = s2u(&Ah[wm + mt * 16 + a_r][ks + a_k8]);
                LDSM4(ah[mt][0], ah[mt][1], ah[mt][2], ah[mt][3], ad);
                uint32_t ad2 = s2u(&Al[wm + mt * 16 + a_r][ks + a_k8]);
                LDSM4(al[mt][0], al[mt][1], al[mt][2], al[mt][3], ad2);
            }
#pragma unroll
            for (int p = 0; p < 2; p++) {
                uint32_t r0, r1, r2, r3;
                uint32_t bd = s2u(&Bh[wn + p * 16 + b_sub * 8 + b_r][ks + b_kh]);
                LDSM4(r0, r1, r2, r3, bd);
                bh[2 * p][0] = r0; bh[2 * p][1] = r1;
                bh[2 * p + 1][0] = r2; bh[2 * p + 1][1] = r3;
                uint32_t bd2 = s2u(&Bl[wn + p * 16 + b_sub * 8 + b_r][ks + b_kh]);
                LDSM4(r0, r1, r2, r3, bd2);
                bl[2 * p][0] = r0; bl[2 * p][1] = r1;
                bl[2 * p + 1][0] = r2; bl[2 * p + 1][1] = r3;
            }
#pragma unroll
            for (int mt = 0; mt < 2; mt++)
#pragma unroll
                for (int nt = 0; nt < 4; nt++) {
                    MMA16816(acc[mt][nt], ah[mt], bh[nt][0], bh[nt][1]);
                    MMA16816(acc[mt][nt], ah[mt], bl[nt][0], bl[nt][1]);
                    MMA16816(acc[mt][nt], al[mt], bh[nt][0], bh[nt][1]);
                }
        }
    }

    // ---- epilogue ----
    int gid = lane >> 2, tig = lane & 3;
#pragma unroll
    for (int mt = 0; mt < 2; mt++) {
        int r0 = wm + mt * 16 + gid;
        int r1 = r0 + 8;
        int g0 = rowids[r0];
        int g1 = rowids[r1];
#pragma unroll
        for (int nt = 0; nt < 4; nt++) {
            int col = l_base + wn + nt * 8 + tig * 2;
            if (g0 >= 0)
                *(float2*)(out + (size_t)g0 * L_N + col) =
                    make_float2(acc[mt][nt][0], acc[mt][nt][1]);
            if (g1 >= 0)
                *(float2*)(out + (size_t)g1 * L_N + col) =
                    make_float2(acc[mt][nt][2], acc[mt][nt][3]);
        }
    }
}

// ---------------- launch ----------------
extern "C" void kernel_launch(void* const* d_in, const int* in_sizes, int n_in,
                              void* d_out, int out_size) {
    const float* hidden = (const float*)d_in[0];
    const float* envs   = (const float*)d_in[1];
    const int*   idx32  = (const int*)d_in[2];
    const float* gumbel = (const float*)d_in[3];
    const float* W      = (const float*)d_in[4];
    float* out = (float*)d_out;

    init_kernel<<<1, 32>>>();
    select_kernel<<<(B_N + 255) / 256, 256>>>(envs, idx32, gumbel);
    penalty_kernel<<<256, 256>>>(W);

    dim3 ggrid(L_N / TN, B_N / TM, E_N);
    gemm_kernel<<<ggrid, 256>>>(hidden, W, out);

    if (out_size > B_N * L_N)
        finalize_kernel<<<1, 32>>>(out + (size_t)B_N * L_N);
}

// round 4
// speedup vs baseline: 4.3515x; 1.0533x over previous
#include <cuda_runtime.h>
#include <cuda_bf16.h>
#include <cstdint>

#define B_N 2048
#define H_N 4096
#define E_N 8
#define L_N 512

// ---------------- scratch ----------------
__device__ int   g_counts[E_N];
__device__ int   g_rows[E_N][B_N];
__device__ float g_pen[25];

__device__ __align__(256) __nv_bfloat16 g_hid_hi[B_N * H_N];
__device__ __align__(256) __nv_bfloat16 g_hid_lo[B_N * H_N];
__device__ __align__(256) __nv_bfloat16 g_W_hi[E_N * L_N * H_N];
__device__ __align__(256) __nv_bfloat16 g_W_lo[E_N * L_N * H_N];

__global__ void init_kernel() {
    int t = threadIdx.x;
    if (t < E_N) g_counts[t] = 0;
    if (t < 25)  g_pen[t]    = 0.0f;
}

// ---------------- expert selection ----------------
__global__ void select_kernel(const float* __restrict__ envs,
                              const int* __restrict__ idx32,
                              const float* __restrict__ gumbel) {
    int b = blockIdx.x * blockDim.x + threadIdx.x;
    if (b >= B_N) return;
    int stride = (idx32[1] == 0) ? 2 : 1;   // int64-on-disk detection (idx = arange)
    int r = idx32[(size_t)b * stride];
    if (r < 0) r = 0;
    if (r >= B_N) r = B_N - 1;
    const float* ev = envs   + (size_t)r * E_N;
    const float* gv = gumbel + (size_t)b * E_N;
    float best = ev[0] + gv[0];
    int be = 0;
#pragma unroll
    for (int e = 1; e < E_N; e++) {
        float v = ev[e] + gv[e];
        if (v > best) { best = v; be = e; }
    }
    int pos = atomicAdd(&g_counts[be], 1);
    g_rows[be][pos] = b;
}

// ---------------- hidden -> bf16 hi/lo ----------------
__device__ __forceinline__ void split4(float4 v, uint2& ph, uint2& pl) {
    __nv_bfloat162 h01 = __floats2bfloat162_rn(v.x, v.y);
    __nv_bfloat162 h23 = __floats2bfloat162_rn(v.z, v.w);
    __nv_bfloat162 l01 = __floats2bfloat162_rn(v.x - __bfloat162float(h01.x),
                                               v.y - __bfloat162float(h01.y));
    __nv_bfloat162 l23 = __floats2bfloat162_rn(v.z - __bfloat162float(h23.x),
                                               v.w - __bfloat162float(h23.y));
    ph.x = *reinterpret_cast<uint32_t*>(&h01);
    ph.y = *reinterpret_cast<uint32_t*>(&h23);
    pl.x = *reinterpret_cast<uint32_t*>(&l01);
    pl.y = *reinterpret_cast<uint32_t*>(&l23);
}

__global__ void __launch_bounds__(256)
convert_hidden_kernel(const float* __restrict__ hidden) {
    const int n4 = B_N * H_N / 4;
    const float4* hv = (const float4*)hidden;
    uint2* hh = (uint2*)g_hid_hi;
    uint2* hl = (uint2*)g_hid_lo;
    int stride = gridDim.x * blockDim.x;
    for (int i = blockIdx.x * blockDim.x + threadIdx.x; i < n4; i += stride) {
        uint2 ph, pl;
        split4(hv[i], ph, pl);
        hh[i] = ph;
        hl[i] = pl;
    }
}

// ---------------- penalty + W -> bf16 hi/lo (fused single pass) ----------------
__global__ void __launch_bounds__(256)
penalty_kernel(const float* __restrict__ W) {
    const int LH4 = (L_N * H_N) / 4;
    const float4* Wv = (const float4*)W;
    uint2* wh = (uint2*)g_W_hi;
    uint2* wl = (uint2*)g_W_lo;

    float q[8], c[8], l1[8], ss = 0.0f;
#pragma unroll
    for (int e = 0; e < 8; e++) { q[e] = 0.f; c[e] = 0.f; l1[e] = 0.f; }

    int stride = gridDim.x * blockDim.x;
    for (int i = blockIdx.x * blockDim.x + threadIdx.x; i < LH4; i += stride) {
        float4 w[8];
#pragma unroll
        for (int e = 0; e < 8; e++) w[e] = Wv[(size_t)e * LH4 + i];
#pragma unroll
        for (int e = 0; e < 8; e++) {
            uint2 ph, pl;
            split4(w[e], ph, pl);
            wh[(size_t)e * LH4 + i] = ph;
            wl[(size_t)e * LH4 + i] = pl;
        }
#pragma unroll
        for (int comp = 0; comp < 4; comp++) {
            float we[8];
#pragma unroll
            for (int e = 0; e < 8; e++) {
                float4 t = w[e];
                we[e] = (comp == 0) ? t.x : (comp == 1) ? t.y : (comp == 2) ? t.z : t.w;
            }
            float s = 0.f;
#pragma unroll
            for (int e = 0; e < 8; e++) s += we[e];
            ss = fmaf(s, s, ss);
#pragma unroll
            for (int e = 0; e < 8; e++) {
                q[e]  = fmaf(we[e], we[e], q[e]);
                c[e]  = fmaf(we[e], s,     c[e]);
                l1[e] += fabsf(we[e]);
            }
        }
    }

    __shared__ float red[25][264];
    int tid = threadIdx.x;
#pragma unroll
    for (int e = 0; e < 8; e++) {
        red[e][tid]      = q[e];
        red[8 + e][tid]  = c[e];
        red[16 + e][tid] = l1[e];
    }
    red[24][tid] = ss;
    __syncthreads();
    if (tid < 25) {
        float s = 0.f;
#pragma unroll 8
        for (int j = 0; j < 256; j++) s += red[tid][j];
        atomicAdd(&g_pen[tid], s);
    }
}

__global__ void finalize_kernel(float* __restrict__ pen_out) {
    if (threadIdx.x == 0) {
        float acc = 0.f;
        float ss = g_pen[24];
#pragma unroll
        for (int e = 0; e < 8; e++) {
            float diff = g_pen[e] - 0.25f * g_pen[8 + e] + ss * (1.0f / 64.0f);
            float l1 = g_pen[16 + e];
            acc += diff / (l1 * l1);
        }
        pen_out[0] = acc * 0.125f;
    }
}

// ---------------- tensor-core grouped GEMM (pre-split bf16, cp.async pipeline) --
// CTA tile 128(M) x 64(N) x 64(K); 256 threads = 8 warps (4M x 2N), warp 32x32.
// smem per stage (halves): Ah 8192 | Al 8192 | Bh 4096 | Bl 4096 = 48KB; 2 stages.
// Layout: row stride 64 halves (128B), 16B chunks XOR-swizzled: phys = c ^ (row&7).

#define TM 128
#define TN 64
#define TK 64
#define STG_H 24576   // halves per stage

__device__ __forceinline__ uint32_t s2u(const void* p) {
    return (uint32_t)__cvta_generic_to_shared(p);
}

__device__ __forceinline__ void cp16(__nv_bfloat16* smem, const __nv_bfloat16* g, bool pred) {
    uint32_t s = s2u(smem);
    int sz = pred ? 16 : 0;
    asm volatile("cp.async.cg.shared.global [%0], [%1], 16, %2;"
                 :: "r"(s), "l"(g), "r"(sz));
}

#define LDSM4(r0, r1, r2, r3, a) \
    asm volatile("ldmatrix.sync.aligned.m8n8.x4.shared.b16 {%0,%1,%2,%3}, [%4];" \
                 : "=r"(r0), "=r"(r1), "=r"(r2), "=r"(r3) : "r"(a))

#define MMA16816(d, A, b0, b1) \
    asm volatile("mma.sync.aligned.m16n8k16.row.col.f32.bf16.bf16.f32 " \
                 "{%0,%1,%2,%3}, {%4,%5,%6,%7}, {%8,%9}, {%0,%1,%2,%3};" \
                 : "+f"((d)[0]), "+f"((d)[1]), "+f"((d)[2]), "+f"((d)[3]) \
                 : "r"((A)[0]), "r"((A)[1]), "r"((A)[2]), "r"((A)[3]), \
                   "r"(b0), "r"(b1))

extern __shared__ __nv_bfloat16 dsmem[];

__global__ void __launch_bounds__(256, 2)
gemm_kernel(float* __restrict__ out) {
    __shared__ int rowids[TM];

    int e = blockIdx.z;
    int cnt = g_counts[e];
    int m_base = blockIdx.y * TM;
    if (m_base >= cnt) return;
    int l_base = blockIdx.x * TN;
    int tid = threadIdx.x;

    if (tid < TM) {
        int i = m_base + tid;
        rowids[tid] = (i < cnt) ? g_rows[e][i] : -1;
    }
    __syncthreads();

    // ---- loader setup ----
    int lrow = tid >> 3;          // 0..31
    int lcc  = tid & 7;           // 16B chunk within row
    int lphys = lcc;              // phys chunk = lcc ^ (row&7); row&7 == lrow&7 per i? no:
    // rows for A chunks: lrow + i*32 -> (row&7) constant across i (32 ≡ 0 mod 8)
    int lxr = lrow & 7;
    lphys = lcc ^ lxr;

    const __nv_bfloat16* gAh[4];
    const __nv_bfloat16* gAl[4];
    bool apred[4];
#pragma unroll
    for (int i = 0; i < 4; i++) {
        int row = lrow + i * 32;
        int g = rowids[row];
        apred[i] = (g >= 0);
        size_t off = (size_t)(apred[i] ? g : 0) * H_N + lcc * 8;
        gAh[i] = g_hid_hi + off;
        gAl[i] = g_hid_lo + off;
    }
    const __nv_bfloat16* gBh[2];
    const __nv_bfloat16* gBl[2];
#pragma unroll
    for (int i = 0; i < 2; i++) {
        int row = lrow + i * 32;
        size_t off = ((size_t)e * L_N + l_base + row) * H_N + lcc * 8;
        gBh[i] = g_W_hi + off;
        gBl[i] = g_W_lo + off;
    }
    // smem write offsets (halves), fixed per thread per i
    int sA[4], sB[2];
#pragma unroll
    for (int i = 0; i < 4; i++) sA[i] = (lrow + i * 32) * 64 + lphys * 8;
#pragma unroll
    for (int i = 0; i < 2; i++) sB[i] = (lrow + i * 32) * 64 + lphys * 8;

    int wid = tid >> 5, lane = tid & 31;
    int wm = (wid & 3) * 32;
    int wn = (wid >> 2) * 32;

    float acc[2][4][4];
#pragma unroll
    for (int mt = 0; mt < 2; mt++)
#pragma unroll
        for (int nt = 0; nt < 4; nt++)
#pragma unroll
            for (int j = 0; j < 4; j++) acc[mt][nt][j] = 0.f;

    // ldmatrix per-thread row geometry
    int a_r = lane & 15, a_h = lane >> 4;          // a_h: k-half select
    int b_g = lane >> 3, b_sub = b_g >> 1, b_h = b_g & 1, b_r = lane & 7;

    int arow[2], axr[2];
#pragma unroll
    for (int mt = 0; mt < 2; mt++) {
        int r = wm + mt * 16 + a_r;
        arow[mt] = r * 64; axr[mt] = r & 7;
    }
    int brow[2], bxr[2];
#pragma unroll
    for (int p = 0; p < 2; p++) {
        int r = wn + p * 16 + b_sub * 8 + b_r;
        brow[p] = r * 64; bxr[p] = r & 7;
    }

    const int NIT = H_N / TK;   // 64

    // preload stage 0
    {
        __nv_bfloat16* s = dsmem;
#pragma unroll
        for (int i = 0; i < 4; i++) {
            cp16(s + sA[i], gAh[i], apred[i]);
            cp16(s + 8192 + sA[i], gAl[i], apred[i]);
        }
#pragma unroll
        for (int i = 0; i < 2; i++) {
            cp16(s + 16384 + sB[i], gBh[i], true);
            cp16(s + 20480 + sB[i], gBl[i], true);
        }
        asm volatile("cp.async.commit_group;");
    }

    for (int it = 0; it < NIT; it++) {
        int cur = it & 1;
        if (it + 1 < NIT) {
            __nv_bfloat16* s = dsmem + (cur ^ 1) * STG_H;
            int k0 = (it + 1) * TK;
#pragma unroll
            for (int i = 0; i < 4; i++) {
                cp16(s + sA[i], gAh[i] + k0, apred[i]);
                cp16(s + 8192 + sA[i], gAl[i] + k0, apred[i]);
            }
#pragma unroll
            for (int i = 0; i < 2; i++) {
                cp16(s + 16384 + sB[i], gBh[i] + k0, true);
                cp16(s + 20480 + sB[i], gBl[i] + k0, true);
            }
        }
        asm volatile("cp.async.commit_group;");
        asm volatile("cp.async.wait_group 1;");
        __syncthreads();

        __nv_bfloat16* AH = dsmem + cur * STG_H;
        __nv_bfloat16* AL = AH + 8192;
        __nv_bfloat16* BH = AL + 8192;
        __nv_bfloat16* BL = BH + 4096;

#pragma unroll
        for (int s4 = 0; s4 < 4; s4++) {         // k16 steps within TK=64
            uint32_t ah[2][4], al[2][4], bh[4][2], bl[4][2];
#pragma unroll
            for (int mt = 0; mt < 2; mt++) {
                int ch = (2 * s4 + a_h) ^ axr[mt];
                uint32_t ad = s2u(AH + arow[mt] + ch * 8);
                LDSM4(ah[mt][0], ah[mt][1], ah[mt][2], ah[mt][3], ad);
                uint32_t ad2 = s2u(AL + arow[mt] + ch * 8);
                LDSM4(al[mt][0], al[mt][1], al[mt][2], al[mt][3], ad2);
            }
#pragma unroll
            for (int p = 0; p < 2; p++) {
                int ch = (2 * s4 + b_h) ^ bxr[p];
                uint32_t r0, r1, r2, r3;
                uint32_t bd = s2u(BH + brow[p] + ch * 8);
                LDSM4(r0, r1, r2, r3, bd);
                bh[2 * p][0] = r0; bh[2 * p][1] = r1;
                bh[2 * p + 1][0] = r2; bh[2 * p + 1][1] = r3;
                uint32_t bd2 = s2u(BL + brow[p] + ch * 8);
                LDSM4(r0, r1, r2, r3, bd2);
                bl[2 * p][0] = r0; bl[2 * p][1] = r1;
                bl[2 * p + 1][0] = r2; bl[2 * p + 1][1] = r3;
            }
#pragma unroll
            for (int mt = 0; mt < 2; mt++)
#pragma unroll
                for (int nt = 0; nt < 4; nt++) {
                    MMA16816(acc[mt][nt], ah[mt], bh[nt][0], bh[nt][1]);
                    MMA16816(acc[mt][nt], ah[mt], bl[nt][0], bl[nt][1]);
                    MMA16816(acc[mt][nt], al[mt], bh[nt][0], bh[nt][1]);
                }
        }
        __syncthreads();
    }

    // ---- epilogue ----
    int gid = lane >> 2, tig = lane & 3;
#pragma unroll
    for (int mt = 0; mt < 2; mt++) {
        int r0 = wm + mt * 16 + gid;
        int r1 = r0 + 8;
        int g0 = rowids[r0];
        int g1 = rowids[r1];
#pragma unroll
        for (int nt = 0; nt < 4; nt++) {
            int col = l_base + wn + nt * 8 + tig * 2;
            if (g0 >= 0)
                *(float2*)(out + (size_t)g0 * L_N + col) =
                    make_float2(acc[mt][nt][0], acc[mt][nt][1]);
            if (g1 >= 0)
                *(float2*)(out + (size_t)g1 * L_N + col) =
                    make_float2(acc[mt][nt][2], acc[mt][nt][3]);
        }
    }
}

// ---------------- launch ----------------
extern "C" void kernel_launch(void* const* d_in, const int* in_sizes, int n_in,
                              void* d_out, int out_size) {
    const float* hidden = (const float*)d_in[0];
    const float* envs   = (const float*)d_in[1];
    const int*   idx32  = (const int*)d_in[2];
    const float* gumbel = (const float*)d_in[3];
    const float* W      = (const float*)d_in[4];
    float* out = (float*)d_out;

    cudaFuncSetAttribute(gemm_kernel,
                         cudaFuncAttributeMaxDynamicSharedMemorySize, 2 * STG_H * 2);

    init_kernel<<<1, 32>>>();
    select_kernel<<<(B_N + 255) / 256, 256>>>(envs, idx32, gumbel);
    convert_hidden_kernel<<<1024, 256>>>(hidden);
    penalty_kernel<<<512, 256>>>(W);

    dim3 ggrid(L_N / TN, B_N / TM, E_N);
    gemm_kernel<<<ggrid, 256, 2 * STG_H * 2>>>(out);

    if (out_size > B_N * L_N)
        finalize_kernel<<<1, 32>>>(out + (size_t)B_N * L_N);
}